// round 7
// baseline (speedup 1.0000x reference)
#include <cuda_runtime.h>

// FraudGNN: 2-layer GCN, N=1M nodes (2 feats), E=32M edges ([2,E] int32 on-device).
// Single persistent kernel, 7 phases separated by software grid barriers.
// Algebra: aggregate in INPUT space (GCNConv linear), dinv folded into node vecs,
// self-loops folded into accumulator init. LTS-bound: 5 L2 ops/edge floor.
//
// Persistent-kernel L1 rule: arrays mutated by REDs after STG (g_deg, g_agg, out)
// are re-read with __ldcg (L1 is NOT coherent with L2 atomics within one launch).

#define NMAX 1000000

__device__ float    g_deg [NMAX];
__device__ float    g_dinv[NMAX];
__device__ float2   g_u   [NMAX];
__device__ float2   g_agg [NMAX];
__device__ float    g_v   [NMAX];
__device__ int      g_is_i32;
__device__ unsigned g_cnt;    // monotonic barrier counter (never reset)
__device__ unsigned g_epoch;  // counter value at start of this run

__device__ __forceinline__ float2 ldcg_f2(const float2* p) {
    float2 r;
    asm volatile("ld.global.cg.v2.f32 {%0,%1}, [%2];" : "=f"(r.x), "=f"(r.y) : "l"(p));
    return r;
}
__device__ __forceinline__ float ldcg_f(const float* p) {
    float r;
    asm volatile("ld.global.cg.f32 %0, [%1];" : "=f"(r) : "l"(p));
    return r;
}

__device__ __forceinline__ void grid_bar(unsigned E0, unsigned k) {
    __syncthreads();
    if (threadIdx.x == 0) {
        __threadfence();                       // release prior STG/RED
        atomicAdd(&g_cnt, 1u);
        unsigned tgt = E0 + k * gridDim.x;
        while ((int)(*(volatile unsigned*)&g_cnt - tgt) < 0) __nanosleep(64);
        __threadfence();                       // acquire
    }
    __syncthreads();
}

__global__ void __launch_bounds__(256, 6)
k_fused(const float* __restrict__ x, const void* __restrict__ ei,
        const float* __restrict__ W1, const float* __restrict__ b1,
        const float* __restrict__ W2, const float* __restrict__ b2,
        float* __restrict__ out, unsigned n, long long E) {
    const unsigned tid  = threadIdx.x;
    const unsigned gtid = blockIdx.x * 256u + tid;
    const unsigned gsz  = gridDim.x * 256u;
    const unsigned E0   = g_epoch;             // stable: only written at end of prior run

    // ---------------- Phase 0: zero deg + dtype detect ----------------
    {
        unsigned nq = (n + 3u) / 4u;
        for (unsigned i = gtid; i < nq; i += gsz) {
            if (4u * i + 3u < n) ((float4*)g_deg)[i] = make_float4(0.f, 0.f, 0.f, 0.f);
            else for (unsigned k = 4u * i; k < n; k++) g_deg[k] = 0.0f;
        }
        if (blockIdx.x == 0) {
            // int64 indices < 2^31 have zero odd 32-bit words; int32 odd words are indices
            const unsigned* w = (const unsigned*)ei;
            unsigned long long nwords = 2ull * (unsigned long long)E;
            int det = 0;
#pragma unroll
            for (int k = 0; k < 8; k++) {
                unsigned long long p = 2ull * (tid + 256u * k) + 1ull;
                if (p < nwords) det |= (w[p] != 0u);
            }
            int any = __syncthreads_or(det);
            if (tid == 0) g_is_i32 = any ? 1 : 0;
        }
    }
    grid_bar(E0, 1);
    const int is32 = g_is_i32;

    // ---------------- Phase 1: degree (dst only) ----------------
    {
        const unsigned noct = (unsigned)((E + 7) / 8);
        for (unsigned q = gtid; q < noct; q += gsz) {
            long long e0 = 8ll * q;
            if (is32 && e0 + 8 <= E) {
                const int* p = (const int*)ei + E;      // dst
                int4 v0 = __ldcs((const int4*)(p + e0));
                int4 v1 = __ldcs((const int4*)(p + e0) + 1);
                int d[8] = {v0.x, v0.y, v0.z, v0.w, v1.x, v1.y, v1.z, v1.w};
#pragma unroll
                for (int k = 0; k < 8; k++)
                    if ((unsigned)d[k] < n) atomicAdd(&g_deg[d[k]], 1.0f);
            } else {
                for (long long e = e0; e < e0 + 8 && e < E; e++) {
                    int d = is32 ? ((const int*)ei)[E + e]
                                 : (int)((const long long*)ei)[E + e];
                    if ((unsigned)d < n) atomicAdd(&g_deg[d], 1.0f);
                }
            }
        }
    }
    grid_bar(E0, 2);

    // ---------------- Phase 2: node pass 1 (dinv, u, agg init) ----------------
    {
        unsigned np = (n + 1u) / 2u;
        for (unsigned i = gtid; i < np; i += gsz) {
            unsigned i0 = 2u * i;
            if (i0 + 1u < n) {
                float2 dg = make_float2(ldcg_f(&g_deg[i0]), ldcg_f(&g_deg[i0 + 1]));
                float4 xv = ((const float4*)x)[i];
                float di0 = rsqrtf(dg.x + 1.0f);
                float di1 = rsqrtf(dg.y + 1.0f);
                ((float2*)g_dinv)[i] = make_float2(di0, di1);
                float4 u = make_float4(xv.x * di0, xv.y * di0, xv.z * di1, xv.w * di1);
                ((float4*)g_u)[i]   = u;
                ((float4*)g_agg)[i] = u;       // self-loop contribution
            } else {
                float dinv = rsqrtf(ldcg_f(&g_deg[i0]) + 1.0f);
                g_dinv[i0] = dinv;
                float2 xv = ((const float2*)x)[i0];
                float2 u  = make_float2(xv.x * dinv, xv.y * dinv);
                g_u[i0] = u; g_agg[i0] = u;
            }
        }
    }
    grid_bar(E0, 3);

    // ---------------- Phase 3: edge pass 1 (agg += u[src], float2 RED) ----------------
    {
        const unsigned noct = (unsigned)((E + 7) / 8);
        for (unsigned q = gtid; q < noct; q += gsz) {
            long long e0 = 8ll * q;
            if (is32 && e0 + 8 <= E) {
                const int* ps = (const int*)ei;
                const int* pd = (const int*)ei + E;
                int4 s0 = __ldcs((const int4*)(ps + e0));
                int4 d0 = __ldcs((const int4*)(pd + e0));
                int4 s1 = __ldcs((const int4*)(ps + e0) + 1);
                int4 d1 = __ldcs((const int4*)(pd + e0) + 1);
                {
                    int s[4] = {s0.x, s0.y, s0.z, s0.w};
                    int d[4] = {d0.x, d0.y, d0.z, d0.w};
                    float2 u[4];
#pragma unroll
                    for (int k = 0; k < 4; k++)
                        u[k] = ((unsigned)s[k] < n) ? __ldg(&g_u[s[k]]) : make_float2(0.f, 0.f);
#pragma unroll
                    for (int k = 0; k < 4; k++)
                        if ((unsigned)s[k] < n && (unsigned)d[k] < n)
                            atomicAdd(&g_agg[d[k]], u[k]);
                }
                {
                    int s[4] = {s1.x, s1.y, s1.z, s1.w};
                    int d[4] = {d1.x, d1.y, d1.z, d1.w};
                    float2 u[4];
#pragma unroll
                    for (int k = 0; k < 4; k++)
                        u[k] = ((unsigned)s[k] < n) ? __ldg(&g_u[s[k]]) : make_float2(0.f, 0.f);
#pragma unroll
                    for (int k = 0; k < 4; k++)
                        if ((unsigned)s[k] < n && (unsigned)d[k] < n)
                            atomicAdd(&g_agg[d[k]], u[k]);
                }
            } else {
                for (long long e = e0; e < e0 + 8 && e < E; e++) {
                    int s = is32 ? ((const int*)ei)[e]     : (int)((const long long*)ei)[e];
                    int d = is32 ? ((const int*)ei)[E + e] : (int)((const long long*)ei)[E + e];
                    if ((unsigned)s < n && (unsigned)d < n)
                        atomicAdd(&g_agg[d], __ldg(&g_u[s]));
                }
            }
        }
    }
    grid_bar(E0, 4);

    // ---------------- Phase 4: node pass 2 (MLP -> v, out init) ----------------
    {
        unsigned np = (n + 1u) / 2u;
        for (unsigned i = gtid; i < np; i += gsz) {
            unsigned i0 = 2u * i;
            unsigned lim = (i0 + 1u < n) ? 2u : 1u;
            float vv[2];
#pragma unroll
            for (unsigned m = 0; m < 2; m++) {
                if (m >= lim) break;
                unsigned idx = i0 + m;
                float dinv = g_dinv[idx];
                float2 a   = ldcg_f2(&g_agg[idx]);
                float ax = a.x * dinv, ay = a.y * dinv;
                float t = 0.0f;
#pragma unroll
                for (int j = 0; j < 8; j++) {
                    float y = fmaf(ax, __ldg(&W1[j]), fmaf(ay, __ldg(&W1[8 + j]), __ldg(&b1[j])));
                    y = fmaxf(y, 0.0f);
                    t = fmaf(y, __ldg(&W2[j]), t);
                }
                vv[m] = t * dinv;
            }
            if (lim == 2) {
                ((float2*)g_v)[i] = make_float2(vv[0], vv[1]);
                ((float2*)out)[i] = make_float2(vv[0], vv[1]);
            } else {
                g_v[i0] = vv[0];
                out[i0] = vv[0];
            }
        }
    }
    grid_bar(E0, 5);

    // ---------------- Phase 5: edge pass 2 (out += v[src]) ----------------
    {
        const unsigned noct = (unsigned)((E + 7) / 8);
        for (unsigned q = gtid; q < noct; q += gsz) {
            long long e0 = 8ll * q;
            if (is32 && e0 + 8 <= E) {
                const int* ps = (const int*)ei;
                const int* pd = (const int*)ei + E;
                int4 s0 = __ldcs((const int4*)(ps + e0));
                int4 d0 = __ldcs((const int4*)(pd + e0));
                int4 s1 = __ldcs((const int4*)(ps + e0) + 1);
                int4 d1 = __ldcs((const int4*)(pd + e0) + 1);
                int s[8] = {s0.x, s0.y, s0.z, s0.w, s1.x, s1.y, s1.z, s1.w};
                int d[8] = {d0.x, d0.y, d0.z, d0.w, d1.x, d1.y, d1.z, d1.w};
                float v[8];
#pragma unroll
                for (int k = 0; k < 8; k++)
                    v[k] = ((unsigned)s[k] < n) ? __ldg(&g_v[s[k]]) : 0.0f;
#pragma unroll
                for (int k = 0; k < 8; k++)
                    if ((unsigned)s[k] < n && (unsigned)d[k] < n)
                        atomicAdd(&out[d[k]], v[k]);
            } else {
                for (long long e = e0; e < e0 + 8 && e < E; e++) {
                    int s = is32 ? ((const int*)ei)[e]     : (int)((const long long*)ei)[e];
                    int d = is32 ? ((const int*)ei)[E + e] : (int)((const long long*)ei)[E + e];
                    if ((unsigned)s < n && (unsigned)d < n)
                        atomicAdd(&out[d], __ldg(&g_v[s]));
                }
            }
        }
    }
    grid_bar(E0, 6);

    // ---------------- Phase 6: scale + sigmoid; epoch update ----------------
    {
        float bb = __ldg(b2);
        unsigned np = (n + 1u) / 2u;
        for (unsigned i = gtid; i < np; i += gsz) {
            unsigned i0 = 2u * i;
            if (i0 + 1u < n) {
                float o0 = ldcg_f(&out[i0]);
                float o1 = ldcg_f(&out[i0 + 1]);
                float2 di = ((const float2*)g_dinv)[i];
                float z0 = fmaf(di.x, o0, bb);
                float z1 = fmaf(di.y, o1, bb);
                ((float2*)out)[i] = make_float2(1.0f / (1.0f + __expf(-z0)),
                                                1.0f / (1.0f + __expf(-z1)));
            } else {
                float z = fmaf(g_dinv[i0], ldcg_f(&out[i0]), bb);
                out[i0] = 1.0f / (1.0f + __expf(-z));
            }
        }
        if (gtid == 0) g_epoch = E0 + 6u * gridDim.x;   // monotonic; no resets
    }
}

// ---------------------------------------------------------------- launch
extern "C" void kernel_launch(void* const* d_in, const int* in_sizes, int n_in,
                              void* d_out, int out_size) {
    const float* x  = (const float*)d_in[0];
    const void*  ei = d_in[1];
    const float* W1 = (const float*)d_in[2];
    const float* b1 = (const float*)d_in[3];
    const float* W2 = (const float*)d_in[4];
    const float* b2 = (const float*)d_in[5];
    float* out = (float*)d_out;

    unsigned  n = (unsigned)(in_sizes[0] / 2);  // x is [N, 2]
    long long E = (long long)in_sizes[1] / 2;   // edge_index is [2, E]

    int dev = 0, sms = 148;
    cudaGetDevice(&dev);
    cudaDeviceGetAttribute(&sms, cudaDevAttrMultiProcessorCount, dev);
    int blocks = sms * 6;                       // co-resident by __launch_bounds__(256,6)

    k_fused<<<blocks, 256>>>(x, ei, W1, b1, W2, b2, out, n, E);
}

// round 8
// speedup vs baseline: 1.0550x; 1.0550x over previous
#include <cuda_runtime.h>

// FraudGNN: 2-layer GCN, N=1M nodes (2 feats), E=32M edges ([2,E] int32 on-device).
// Single persistent kernel, 7 phases, grid barriers between. Edge phases use
// DYNAMIC work stealing (global chunk counter) so the barrier pays mean block
// time, not max (R7's static partition lost ~280us to barrier skew).
//
// Persistent-kernel L1 rule: arrays mutated by REDs after STG (g_deg, g_agg, out)
// are re-read with __ldcg (L1 not coherent with L2 atomics within one launch).

#define NMAX 1000000
#define CHUNK 512u   // octets per steal (512*8 = 4096 edges)

__device__ float    g_deg [NMAX];
__device__ float    g_dinv[NMAX];
__device__ float2   g_u   [NMAX];
__device__ float2   g_agg [NMAX];
__device__ float    g_v   [NMAX];
__device__ int      g_is_i32;
__device__ unsigned g_cnt;      // monotonic barrier counter (never reset)
__device__ unsigned g_epoch;    // counter value at start of this run
__device__ unsigned g_work[3];  // steal counters: deg, edge1, edge2 (reset in phase 0)

__device__ __forceinline__ float2 ldcg_f2(const float2* p) {
    float2 r;
    asm volatile("ld.global.cg.v2.f32 {%0,%1}, [%2];" : "=f"(r.x), "=f"(r.y) : "l"(p));
    return r;
}
__device__ __forceinline__ float ldcg_f(const float* p) {
    float r;
    asm volatile("ld.global.cg.f32 %0, [%1];" : "=f"(r) : "l"(p));
    return r;
}

__device__ __forceinline__ void grid_bar(unsigned E0, unsigned k) {
    __syncthreads();
    if (threadIdx.x == 0) {
        __threadfence();                       // release prior STG/RED
        atomicAdd(&g_cnt, 1u);
        unsigned tgt = E0 + k * gridDim.x;
        while ((int)(*(volatile unsigned*)&g_cnt - tgt) < 0) __nanosleep(64);
        __threadfence();                       // acquire
    }
    __syncthreads();
}

__global__ void __launch_bounds__(256, 6)
k_fused(const float* __restrict__ x, const void* __restrict__ ei,
        const float* __restrict__ W1, const float* __restrict__ b1,
        const float* __restrict__ W2, const float* __restrict__ b2,
        float* __restrict__ out, unsigned n, long long E) {
    const unsigned tid  = threadIdx.x;
    const unsigned gtid = blockIdx.x * 256u + tid;
    const unsigned gsz  = gridDim.x * 256u;
    const unsigned E0   = g_epoch;             // stable: written only at end of prior run
    const unsigned noct = (unsigned)((E + 7) / 8);
    __shared__ unsigned s_base;

    // ---------------- Phase 0: zero deg, reset steal counters, dtype detect ----------
    {
        unsigned nq = (n + 3u) / 4u;
        for (unsigned i = gtid; i < nq; i += gsz) {
            if (4u * i + 3u < n) ((float4*)g_deg)[i] = make_float4(0.f, 0.f, 0.f, 0.f);
            else for (unsigned k = 4u * i; k < n; k++) g_deg[k] = 0.0f;
        }
        if (gtid < 3) g_work[gtid] = 0u;
        if (blockIdx.x == 0) {
            // int64 indices < 2^31 have zero odd 32-bit words; int32 odd words are indices
            const unsigned* w = (const unsigned*)ei;
            unsigned long long nwords = 2ull * (unsigned long long)E;
            int det = 0;
#pragma unroll
            for (int k = 0; k < 8; k++) {
                unsigned long long p = 2ull * (tid + 256u * k) + 1ull;
                if (p < nwords) det |= (w[p] != 0u);
            }
            int any = __syncthreads_or(det);
            if (tid == 0) g_is_i32 = any ? 1 : 0;
        }
    }
    grid_bar(E0, 1);
    const int is32 = g_is_i32;

    // ---------------- Phase 1: degree (dst only) — dynamic ----------------
    for (;;) {
        __syncthreads();
        if (tid == 0) s_base = atomicAdd(&g_work[0], CHUNK);
        __syncthreads();
        unsigned base = s_base;
        if (base >= noct) break;
        unsigned end = min(base + CHUNK, noct);
        for (unsigned q = base + tid; q < end; q += 256u) {
            long long e0 = 8ll * q;
            if (is32 && e0 + 8 <= E) {
                const int* p = (const int*)ei + E;      // dst
                int4 v0 = __ldcs((const int4*)(p + e0));
                int4 v1 = __ldcs((const int4*)(p + e0) + 1);
                int d[8] = {v0.x, v0.y, v0.z, v0.w, v1.x, v1.y, v1.z, v1.w};
#pragma unroll
                for (int k = 0; k < 8; k++)
                    if ((unsigned)d[k] < n) atomicAdd(&g_deg[d[k]], 1.0f);
            } else {
                for (long long e = e0; e < e0 + 8 && e < E; e++) {
                    int d = is32 ? ((const int*)ei)[E + e]
                                 : (int)((const long long*)ei)[E + e];
                    if ((unsigned)d < n) atomicAdd(&g_deg[d], 1.0f);
                }
            }
        }
    }
    grid_bar(E0, 2);

    // ---------------- Phase 2: node pass 1 (dinv, u, agg init) — static ----------------
    {
        unsigned np = (n + 1u) / 2u;
        for (unsigned i = gtid; i < np; i += gsz) {
            unsigned i0 = 2u * i;
            if (i0 + 1u < n) {
                float dg0 = ldcg_f(&g_deg[i0]);
                float dg1 = ldcg_f(&g_deg[i0 + 1]);
                float4 xv = ((const float4*)x)[i];
                float di0 = rsqrtf(dg0 + 1.0f);
                float di1 = rsqrtf(dg1 + 1.0f);
                ((float2*)g_dinv)[i] = make_float2(di0, di1);
                float4 u = make_float4(xv.x * di0, xv.y * di0, xv.z * di1, xv.w * di1);
                ((float4*)g_u)[i]   = u;
                ((float4*)g_agg)[i] = u;       // self-loop contribution
            } else {
                float dinv = rsqrtf(ldcg_f(&g_deg[i0]) + 1.0f);
                g_dinv[i0] = dinv;
                float2 xv = ((const float2*)x)[i0];
                float2 u  = make_float2(xv.x * dinv, xv.y * dinv);
                g_u[i0] = u; g_agg[i0] = u;
            }
        }
    }
    grid_bar(E0, 3);

    // ---------------- Phase 3: edge pass 1 (agg += u[src]) — dynamic ----------------
    for (;;) {
        __syncthreads();
        if (tid == 0) s_base = atomicAdd(&g_work[1], CHUNK);
        __syncthreads();
        unsigned base = s_base;
        if (base >= noct) break;
        unsigned end = min(base + CHUNK, noct);
        for (unsigned q = base + tid; q < end; q += 256u) {
            long long e0 = 8ll * q;
            if (is32 && e0 + 8 <= E) {
                const int* ps = (const int*)ei;
                const int* pd = (const int*)ei + E;
                int4 s0 = __ldcs((const int4*)(ps + e0));
                int4 d0 = __ldcs((const int4*)(pd + e0));
                int4 s1 = __ldcs((const int4*)(ps + e0) + 1);
                int4 d1 = __ldcs((const int4*)(pd + e0) + 1);
                int s[8] = {s0.x, s0.y, s0.z, s0.w, s1.x, s1.y, s1.z, s1.w};
                int d[8] = {d0.x, d0.y, d0.z, d0.w, d1.x, d1.y, d1.z, d1.w};
                float2 u[8];
#pragma unroll
                for (int k = 0; k < 8; k++)
                    u[k] = ((unsigned)s[k] < n) ? __ldg(&g_u[s[k]]) : make_float2(0.f, 0.f);
#pragma unroll
                for (int k = 0; k < 8; k++)
                    if ((unsigned)s[k] < n && (unsigned)d[k] < n)
                        atomicAdd(&g_agg[d[k]], u[k]);   // 64-bit vector RED
            } else {
                for (long long e = e0; e < e0 + 8 && e < E; e++) {
                    int s = is32 ? ((const int*)ei)[e]     : (int)((const long long*)ei)[e];
                    int d = is32 ? ((const int*)ei)[E + e] : (int)((const long long*)ei)[E + e];
                    if ((unsigned)s < n && (unsigned)d < n)
                        atomicAdd(&g_agg[d], __ldg(&g_u[s]));
                }
            }
        }
    }
    grid_bar(E0, 4);

    // ---------------- Phase 4: node pass 2 (MLP -> v, out init) — static ----------------
    {
        unsigned np = (n + 1u) / 2u;
        for (unsigned i = gtid; i < np; i += gsz) {
            unsigned i0 = 2u * i;
            unsigned lim = (i0 + 1u < n) ? 2u : 1u;
            float vv[2];
#pragma unroll
            for (unsigned m = 0; m < 2; m++) {
                if (m >= lim) break;
                unsigned idx = i0 + m;
                float dinv = g_dinv[idx];
                float2 a   = ldcg_f2(&g_agg[idx]);
                float ax = a.x * dinv, ay = a.y * dinv;
                float t = 0.0f;
#pragma unroll
                for (int j = 0; j < 8; j++) {
                    float y = fmaf(ax, __ldg(&W1[j]), fmaf(ay, __ldg(&W1[8 + j]), __ldg(&b1[j])));
                    y = fmaxf(y, 0.0f);
                    t = fmaf(y, __ldg(&W2[j]), t);
                }
                vv[m] = t * dinv;
            }
            if (lim == 2) {
                ((float2*)g_v)[i] = make_float2(vv[0], vv[1]);
                ((float2*)out)[i] = make_float2(vv[0], vv[1]);
            } else {
                g_v[i0] = vv[0];
                out[i0] = vv[0];
            }
        }
    }
    grid_bar(E0, 5);

    // ---------------- Phase 5: edge pass 2 (out += v[src]) — dynamic ----------------
    for (;;) {
        __syncthreads();
        if (tid == 0) s_base = atomicAdd(&g_work[2], CHUNK);
        __syncthreads();
        unsigned base = s_base;
        if (base >= noct) break;
        unsigned end = min(base + CHUNK, noct);
        for (unsigned q = base + tid; q < end; q += 256u) {
            long long e0 = 8ll * q;
            if (is32 && e0 + 8 <= E) {
                const int* ps = (const int*)ei;
                const int* pd = (const int*)ei + E;
                int4 s0 = __ldcs((const int4*)(ps + e0));
                int4 d0 = __ldcs((const int4*)(pd + e0));
                int4 s1 = __ldcs((const int4*)(ps + e0) + 1);
                int4 d1 = __ldcs((const int4*)(pd + e0) + 1);
                int s[8] = {s0.x, s0.y, s0.z, s0.w, s1.x, s1.y, s1.z, s1.w};
                int d[8] = {d0.x, d0.y, d0.z, d0.w, d1.x, d1.y, d1.z, d1.w};
                float v[8];
#pragma unroll
                for (int k = 0; k < 8; k++)
                    v[k] = ((unsigned)s[k] < n) ? __ldg(&g_v[s[k]]) : 0.0f;
#pragma unroll
                for (int k = 0; k < 8; k++)
                    if ((unsigned)s[k] < n && (unsigned)d[k] < n)
                        atomicAdd(&out[d[k]], v[k]);
            } else {
                for (long long e = e0; e < e0 + 8 && e < E; e++) {
                    int s = is32 ? ((const int*)ei)[e]     : (int)((const long long*)ei)[e];
                    int d = is32 ? ((const int*)ei)[E + e] : (int)((const long long*)ei)[E + e];
                    if ((unsigned)s < n && (unsigned)d < n)
                        atomicAdd(&out[d], __ldg(&g_v[s]));
                }
            }
        }
    }
    grid_bar(E0, 6);

    // ---------------- Phase 6: scale + sigmoid; epoch update ----------------
    {
        float bb = __ldg(b2);
        unsigned np = (n + 1u) / 2u;
        for (unsigned i = gtid; i < np; i += gsz) {
            unsigned i0 = 2u * i;
            if (i0 + 1u < n) {
                float o0 = ldcg_f(&out[i0]);
                float o1 = ldcg_f(&out[i0 + 1]);
                float2 di = ((const float2*)g_dinv)[i];
                float z0 = fmaf(di.x, o0, bb);
                float z1 = fmaf(di.y, o1, bb);
                ((float2*)out)[i] = make_float2(1.0f / (1.0f + __expf(-z0)),
                                                1.0f / (1.0f + __expf(-z1)));
            } else {
                float z = fmaf(g_dinv[i0], ldcg_f(&out[i0]), bb);
                out[i0] = 1.0f / (1.0f + __expf(-z));
            }
        }
        if (gtid == 0) g_epoch = E0 + 6u * gridDim.x;   // monotonic; no resets
    }
}

// ---------------------------------------------------------------- launch
extern "C" void kernel_launch(void* const* d_in, const int* in_sizes, int n_in,
                              void* d_out, int out_size) {
    const float* x  = (const float*)d_in[0];
    const void*  ei = d_in[1];
    const float* W1 = (const float*)d_in[2];
    const float* b1 = (const float*)d_in[3];
    const float* W2 = (const float*)d_in[4];
    const float* b2 = (const float*)d_in[5];
    float* out = (float*)d_out;

    unsigned  n = (unsigned)(in_sizes[0] / 2);  // x is [N, 2]
    long long E = (long long)in_sizes[1] / 2;   // edge_index is [2, E]

    int dev = 0, sms = 148;
    cudaGetDevice(&dev);
    cudaDeviceGetAttribute(&sms, cudaDevAttrMultiProcessorCount, dev);
    int blocks = sms * 6;                       // co-resident by __launch_bounds__(256,6)

    k_fused<<<blocks, 256>>>(x, ei, W1, b1, W2, b2, out, n, E);
}

// round 9
// speedup vs baseline: 1.3250x; 1.2559x over previous
#include <cuda_runtime.h>

// FraudGNN: 2-layer GCN, N=1M nodes (2 feats), E=32M edges ([2,E] int32 on-device).
// Algebra: GCNConv is linear => aggregate in INPUT space.
//   deg[i]   = indeg(i) + 1 (self loop);  dinv = rsqrt(deg)
//   u[i]     = dinv[i] * x[i]
//   agg1[d]  = dinv[d] * (sum_{s->d} u[s] + u[d])
//   h[i]     = relu(agg1[i] @ W1 + b1);  t[i] = h[i] @ W2;  v[i] = dinv[i]*t[i]
//   out[d]   = sigmoid( dinv[d] * (sum_{s->d} v[s] + v[d]) + b2 )
//
// 5 kernels. g_deg is zero at module load; k_node1 reads each deg and writes 0
// back, restoring the invariant for the next graph replay (deterministic).
// Edge-index dtype (i32 vs i64) detected per-block inside k_deg.
// LTS-bound: 5 L2 ops/edge floor. 8 edges/thread, __ldcs index streams,
// float2 vector REDs in layer 1.

#define NMAX 1000000

__device__ float  g_deg [NMAX];          // zero-init at load; re-zeroed by k_node1
__device__ float  g_dinv[NMAX];
__device__ float2 g_u   [NMAX];
__device__ float2 g_agg [NMAX];
__device__ float  g_v   [NMAX];
__device__ int    g_is_i32;              // published by k_deg blocks (idempotent)

// per-block dtype detect: int64 indices < 2^31 have zero odd 32-bit words;
// int32 odd words are real indices (256 samples => false-negative ~0).
__device__ __forceinline__ int detect_i32(const void* ei, long long E) {
    __shared__ int s_flag;
    const unsigned* w = (const unsigned*)ei;
    unsigned long long nwords = 2ull * (unsigned long long)E;
    int det = 0;
    unsigned long long p = 2ull * threadIdx.x + 1ull;
    if (p < nwords) det = (w[p] != 0u);
    int any = __syncthreads_or(det);
    if (threadIdx.x == 0) s_flag = any;
    __syncthreads();
    return s_flag;
}

// ---------------------------------------------------------------- degree (dst only) + detect
__global__ void k_deg(const void* __restrict__ ei, long long E, int n) {
    int is32 = detect_i32(ei, E);
    if (blockIdx.x == 0 && threadIdx.x == 0) g_is_i32 = is32;  // publish for later kernels
    long long q = (long long)blockIdx.x * blockDim.x + threadIdx.x;
    long long e0 = 8 * q;
    if (e0 >= E) return;
    if (is32 && e0 + 8 <= E) {
        const int* p = (const int*)ei + E;                     // dst
        int4 v0 = __ldcs((const int4*)(p + e0));
        int4 v1 = __ldcs((const int4*)(p + e0) + 1);
        int d[8] = {v0.x, v0.y, v0.z, v0.w, v1.x, v1.y, v1.z, v1.w};
#pragma unroll
        for (int k = 0; k < 8; k++)
            if ((unsigned)d[k] < (unsigned)n) atomicAdd(&g_deg[d[k]], 1.0f);
    } else {
        for (long long e = e0; e < e0 + 8 && e < E; e++) {
            int d = is32 ? ((const int*)ei)[E + e] : (int)((const long long*)ei)[E + e];
            if ((unsigned)d < (unsigned)n) atomicAdd(&g_deg[d], 1.0f);
        }
    }
}

// ---------------------------------------------------------------- node pass 1 (+deg reset)
__global__ void k_node1(const float* __restrict__ x, int n) {
    int i = blockIdx.x * blockDim.x + threadIdx.x;
    int i0 = 2 * i;
    if (i0 >= n) return;
    if (i0 + 1 < n) {
        float2 dg = ((const float2*)g_deg)[i];
        ((float2*)g_deg)[i] = make_float2(0.f, 0.f);   // restore invariant for next call
        float4 xv = ((const float4*)x)[i];
        float di0 = rsqrtf(dg.x + 1.0f);
        float di1 = rsqrtf(dg.y + 1.0f);
        ((float2*)g_dinv)[i] = make_float2(di0, di1);
        float4 u = make_float4(xv.x * di0, xv.y * di0, xv.z * di1, xv.w * di1);
        ((float4*)g_u)[i]   = u;
        ((float4*)g_agg)[i] = u;                       // self-loop contribution
    } else {
        float dg = g_deg[i0];
        g_deg[i0] = 0.0f;
        float dinv = rsqrtf(dg + 1.0f);
        g_dinv[i0] = dinv;
        float2 xv = ((const float2*)x)[i0];
        float2 u  = make_float2(xv.x * dinv, xv.y * dinv);
        g_u[i0] = u; g_agg[i0] = u;
    }
}

// ---------------------------------------------------------------- edge pass 1: agg += u[src]
__global__ void k_edge1(const void* __restrict__ ei, long long E, int n) {
    long long q = (long long)blockIdx.x * blockDim.x + threadIdx.x;
    long long e0 = 8 * q;
    if (e0 >= E) return;
    int is32 = g_is_i32;
    if (is32 && e0 + 8 <= E) {
        const int* ps = (const int*)ei;
        const int* pd = (const int*)ei + E;
        int4 s0 = __ldcs((const int4*)(ps + e0));
        int4 d0 = __ldcs((const int4*)(pd + e0));
        int4 s1 = __ldcs((const int4*)(ps + e0) + 1);
        int4 d1 = __ldcs((const int4*)(pd + e0) + 1);
        int s[8] = {s0.x, s0.y, s0.z, s0.w, s1.x, s1.y, s1.z, s1.w};
        int d[8] = {d0.x, d0.y, d0.z, d0.w, d1.x, d1.y, d1.z, d1.w};
        float2 u[8];
#pragma unroll
        for (int k = 0; k < 8; k++)
            u[k] = ((unsigned)s[k] < (unsigned)n) ? __ldg(&g_u[s[k]]) : make_float2(0.f, 0.f);
#pragma unroll
        for (int k = 0; k < 8; k++)
            if ((unsigned)s[k] < (unsigned)n && (unsigned)d[k] < (unsigned)n)
                atomicAdd(&g_agg[d[k]], u[k]);         // 64-bit vector RED
    } else {
        for (long long e = e0; e < e0 + 8 && e < E; e++) {
            int s = is32 ? ((const int*)ei)[e]     : (int)((const long long*)ei)[e];
            int d = is32 ? ((const int*)ei)[E + e] : (int)((const long long*)ei)[E + e];
            if ((unsigned)s < (unsigned)n && (unsigned)d < (unsigned)n)
                atomicAdd(&g_agg[d], __ldg(&g_u[s]));
        }
    }
}

// ---------------------------------------------------------------- node pass 2: MLP + init out
__global__ void k_node2(const float* __restrict__ W1, const float* __restrict__ b1,
                        const float* __restrict__ W2,
                        float* __restrict__ out, int n) {
    int i = blockIdx.x * blockDim.x + threadIdx.x;
    int i0 = 2 * i;
    if (i0 >= n) return;
    int lim = (i0 + 1 < n) ? 2 : 1;
    float vv[2];
#pragma unroll
    for (int m = 0; m < 2; m++) {
        if (m >= lim) break;
        int idx = i0 + m;
        float dinv = g_dinv[idx];
        float2 a   = g_agg[idx];
        float ax = a.x * dinv, ay = a.y * dinv;
        float t = 0.0f;
#pragma unroll
        for (int j = 0; j < 8; j++) {
            float y = fmaf(ax, __ldg(&W1[j]), fmaf(ay, __ldg(&W1[8 + j]), __ldg(&b1[j])));
            y = fmaxf(y, 0.0f);
            t = fmaf(y, __ldg(&W2[j]), t);
        }
        vv[m] = t * dinv;
    }
    if (lim == 2) {
        ((float2*)g_v)[i] = make_float2(vv[0], vv[1]);
        ((float2*)out)[i] = make_float2(vv[0], vv[1]);  // self-loop init
    } else {
        g_v[i0] = vv[0];
        out[i0] = vv[0];
    }
}

// ---------------------------------------------------------------- edge pass 2: out += v[src]
__global__ void k_edge2(const void* __restrict__ ei, float* __restrict__ out,
                        long long E, int n) {
    long long q = (long long)blockIdx.x * blockDim.x + threadIdx.x;
    long long e0 = 8 * q;
    if (e0 >= E) return;
    int is32 = g_is_i32;
    if (is32 && e0 + 8 <= E) {
        const int* ps = (const int*)ei;
        const int* pd = (const int*)ei + E;
        int4 s0 = __ldcs((const int4*)(ps + e0));
        int4 d0 = __ldcs((const int4*)(pd + e0));
        int4 s1 = __ldcs((const int4*)(ps + e0) + 1);
        int4 d1 = __ldcs((const int4*)(pd + e0) + 1);
        int s[8] = {s0.x, s0.y, s0.z, s0.w, s1.x, s1.y, s1.z, s1.w};
        int d[8] = {d0.x, d0.y, d0.z, d0.w, d1.x, d1.y, d1.z, d1.w};
        float v[8];
#pragma unroll
        for (int k = 0; k < 8; k++)
            v[k] = ((unsigned)s[k] < (unsigned)n) ? __ldg(&g_v[s[k]]) : 0.0f;
#pragma unroll
        for (int k = 0; k < 8; k++)
            if ((unsigned)s[k] < (unsigned)n && (unsigned)d[k] < (unsigned)n)
                atomicAdd(&out[d[k]], v[k]);
    } else {
        for (long long e = e0; e < e0 + 8 && e < E; e++) {
            int s = is32 ? ((const int*)ei)[e]     : (int)((const long long*)ei)[e];
            int d = is32 ? ((const int*)ei)[E + e] : (int)((const long long*)ei)[E + e];
            if ((unsigned)s < (unsigned)n && (unsigned)d < (unsigned)n)
                atomicAdd(&out[d], __ldg(&g_v[s]));
        }
    }
}

// ---------------------------------------------------------------- final: scale + sigmoid
__global__ void k_final(float* __restrict__ out, const float* __restrict__ b2, int n) {
    int i = blockIdx.x * blockDim.x + threadIdx.x;
    int i0 = 2 * i;
    if (i0 >= n) return;
    float bb = __ldg(b2);
    if (i0 + 1 < n) {
        float2 o  = ((const float2*)out)[i];
        float2 di = ((const float2*)g_dinv)[i];
        float z0 = fmaf(di.x, o.x, bb);
        float z1 = fmaf(di.y, o.y, bb);
        ((float2*)out)[i] = make_float2(1.0f / (1.0f + __expf(-z0)),
                                        1.0f / (1.0f + __expf(-z1)));
    } else {
        float z = fmaf(g_dinv[i0], out[i0], bb);
        out[i0] = 1.0f / (1.0f + __expf(-z));
    }
}

// ---------------------------------------------------------------- launch
extern "C" void kernel_launch(void* const* d_in, const int* in_sizes, int n_in,
                              void* d_out, int out_size) {
    const float* x  = (const float*)d_in[0];
    const void*  ei = d_in[1];
    const float* W1 = (const float*)d_in[2];
    const float* b1 = (const float*)d_in[3];
    const float* W2 = (const float*)d_in[4];
    const float* b2 = (const float*)d_in[5];
    float* out = (float*)d_out;

    int       n = in_sizes[0] / 2;            // x is [N, 2]
    long long E = (long long)in_sizes[1] / 2; // edge_index is [2, E]

    const int T = 256;
    int nb_half = ((n + 1) / 2 + T - 1) / T;
    long long noct = (E + 7) / 8;
    int nb_edge = (int)((noct + T - 1) / T);

    k_deg   <<<nb_edge, T>>>(ei, E, n);
    k_node1 <<<nb_half, T>>>(x, n);
    k_edge1 <<<nb_edge, T>>>(ei, E, n);
    k_node2 <<<nb_half, T>>>(W1, b1, W2, out, n);
    k_edge2 <<<nb_edge, T>>>(ei, out, E, n);
    k_final <<<nb_half, T>>>(out, b2, n);
}

// round 10
// speedup vs baseline: 1.3457x; 1.0156x over previous
#include <cuda_runtime.h>

// FraudGNN: 2-layer GCN, N=1M nodes (2 feats), E=32M edges ([2,E] int32 on-device).
// Algebra: GCNConv is linear => aggregate in INPUT space.
//   deg[i]   = indeg(i) + 1 (self loop);  dinv = rsqrt(deg)
//   u[i]     = dinv[i] * x[i]
//   agg1[d]  = dinv[d] * (sum_{s->d} u[s] + u[d])
//   h[i]     = relu(agg1[i] @ W1 + b1);  t[i] = h[i] @ W2;  v[i] = dinv[i]*t[i]
//   out[d]   = sigmoid( dinv[d] * (sum_{s->d} v[s] + v[d]) + b2 )
//
// 6 kernels chained with Programmatic Dependent Launch: downstream kernels do
// their INDEPENDENT preamble loads (edge indices, x, weights) before
// cudaGridDependencySynchronize(), overlapping upstream tail drain.
// g_deg is zero at load; k_node1 re-zeroes it (replay invariant).
// LTS-bound: ~5 L2 sector-ops/edge floor. 8 edges/thread, __ldcs index
// streams, float2 vector REDs in layer 1.

#define NMAX 1000000

__device__ float  g_deg [NMAX];          // zero at load; re-zeroed by k_node1
__device__ float  g_dinv[NMAX];
__device__ float2 g_u   [NMAX];
__device__ float2 g_agg [NMAX];
__device__ float  g_v   [NMAX];
__device__ int    g_is_i32;              // published by k_deg (idempotent)

// ---------------------------------------------------------------- degree (dst only) + detect
__global__ void k_deg(const void* __restrict__ ei, long long E, int n) {
    cudaTriggerProgrammaticLaunchCompletion();
    // dtype detect: int64 indices < 2^31 have zero odd 32-bit words.
    __shared__ int s_flag;
    {
        const unsigned* w = (const unsigned*)ei;
        unsigned long long nwords = 2ull * (unsigned long long)E;
        unsigned long long p = 2ull * threadIdx.x + 1ull;
        int det = (p < nwords) ? (w[p] != 0u) : 0;
        int any = __syncthreads_or(det);
        if (threadIdx.x == 0) s_flag = any;
        __syncthreads();
    }
    int is32 = s_flag;
    if (blockIdx.x == 0 && threadIdx.x == 0) g_is_i32 = is32;
    long long q = (long long)blockIdx.x * blockDim.x + threadIdx.x;
    long long e0 = 8 * q;
    if (e0 >= E) return;
    if (is32 && e0 + 8 <= E) {
        const int* p = (const int*)ei + E;                     // dst
        int4 v0 = __ldcs((const int4*)(p + e0));
        int4 v1 = __ldcs((const int4*)(p + e0) + 1);
        int d[8] = {v0.x, v0.y, v0.z, v0.w, v1.x, v1.y, v1.z, v1.w};
#pragma unroll
        for (int k = 0; k < 8; k++)
            if ((unsigned)d[k] < (unsigned)n) atomicAdd(&g_deg[d[k]], 1.0f);
    } else {
        for (long long e = e0; e < e0 + 8 && e < E; e++) {
            int d = is32 ? ((const int*)ei)[E + e] : (int)((const long long*)ei)[E + e];
            if ((unsigned)d < (unsigned)n) atomicAdd(&g_deg[d], 1.0f);
        }
    }
}

// ---------------------------------------------------------------- node pass 1 (+deg reset)
__global__ void k_node1(const float* __restrict__ x, int n) {
    cudaTriggerProgrammaticLaunchCompletion();
    int i = blockIdx.x * blockDim.x + threadIdx.x;
    int i0 = 2 * i;
    if (i0 >= n) { cudaGridDependencySynchronize(); return; }
    if (i0 + 1 < n) {
        float4 xv = ((const float4*)x)[i];     // independent preamble load
        cudaGridDependencySynchronize();       // wait for k_deg's REDs
        float2 dg = ((const float2*)g_deg)[i];
        ((float2*)g_deg)[i] = make_float2(0.f, 0.f);   // restore replay invariant
        float di0 = rsqrtf(dg.x + 1.0f);
        float di1 = rsqrtf(dg.y + 1.0f);
        ((float2*)g_dinv)[i] = make_float2(di0, di1);
        float4 u = make_float4(xv.x * di0, xv.y * di0, xv.z * di1, xv.w * di1);
        ((float4*)g_u)[i]   = u;
        ((float4*)g_agg)[i] = u;               // self-loop contribution
    } else {
        float2 xv = ((const float2*)x)[i0];
        cudaGridDependencySynchronize();
        float dg = g_deg[i0];
        g_deg[i0] = 0.0f;
        float dinv = rsqrtf(dg + 1.0f);
        g_dinv[i0] = dinv;
        float2 u = make_float2(xv.x * dinv, xv.y * dinv);
        g_u[i0] = u; g_agg[i0] = u;
    }
}

// ---------------------------------------------------------------- edge pass 1: agg += u[src]
__global__ void k_edge1(const void* __restrict__ ei, long long E, int n) {
    cudaTriggerProgrammaticLaunchCompletion();
    long long q = (long long)blockIdx.x * blockDim.x + threadIdx.x;
    long long e0 = 8 * q;
    if (e0 >= E) { cudaGridDependencySynchronize(); return; }
    if (e0 + 8 <= E) {
        // optimistic i32 preamble loads (safe under either dtype; reinterpreted only if i32)
        const int* ps = (const int*)ei;
        const int* pd = (const int*)ei + E;
        int4 s0 = __ldcs((const int4*)(ps + e0));
        int4 d0 = __ldcs((const int4*)(pd + e0));
        int4 s1 = __ldcs((const int4*)(ps + e0) + 1);
        int4 d1 = __ldcs((const int4*)(pd + e0) + 1);
        cudaGridDependencySynchronize();       // wait for k_node1 (g_u, g_agg)
        if (g_is_i32) {
            int s[8] = {s0.x, s0.y, s0.z, s0.w, s1.x, s1.y, s1.z, s1.w};
            int d[8] = {d0.x, d0.y, d0.z, d0.w, d1.x, d1.y, d1.z, d1.w};
            float2 u[8];
#pragma unroll
            for (int k = 0; k < 8; k++)
                u[k] = ((unsigned)s[k] < (unsigned)n) ? __ldg(&g_u[s[k]]) : make_float2(0.f, 0.f);
#pragma unroll
            for (int k = 0; k < 8; k++)
                if ((unsigned)s[k] < (unsigned)n && (unsigned)d[k] < (unsigned)n)
                    atomicAdd(&g_agg[d[k]], u[k]);   // 64-bit vector RED
            return;
        }
    } else {
        cudaGridDependencySynchronize();
    }
    // slow path (i64 or ragged tail)
    int is32 = g_is_i32;
    for (long long e = e0; e < e0 + 8 && e < E; e++) {
        int s = is32 ? ((const int*)ei)[e]     : (int)((const long long*)ei)[e];
        int d = is32 ? ((const int*)ei)[E + e] : (int)((const long long*)ei)[E + e];
        if ((unsigned)s < (unsigned)n && (unsigned)d < (unsigned)n)
            atomicAdd(&g_agg[d], __ldg(&g_u[s]));
    }
}

// ---------------------------------------------------------------- node pass 2: MLP + init out
__global__ void k_node2(const float* __restrict__ W1, const float* __restrict__ b1,
                        const float* __restrict__ W2,
                        float* __restrict__ out, int n) {
    cudaTriggerProgrammaticLaunchCompletion();
    // independent preamble: tiny weight loads
    float w1a[8], w1b[8], bb1[8], w2[8];
#pragma unroll
    for (int j = 0; j < 8; j++) {
        w1a[j] = __ldg(&W1[j]); w1b[j] = __ldg(&W1[8 + j]);
        bb1[j] = __ldg(&b1[j]); w2[j]  = __ldg(&W2[j]);
    }
    cudaGridDependencySynchronize();           // wait for k_edge1 (g_agg)
    int i = blockIdx.x * blockDim.x + threadIdx.x;
    int i0 = 2 * i;
    if (i0 >= n) return;
    int lim = (i0 + 1 < n) ? 2 : 1;
    float vv[2];
#pragma unroll
    for (int m = 0; m < 2; m++) {
        if (m >= lim) break;
        int idx = i0 + m;
        float dinv = g_dinv[idx];
        float2 a   = g_agg[idx];
        float ax = a.x * dinv, ay = a.y * dinv;
        float t = 0.0f;
#pragma unroll
        for (int j = 0; j < 8; j++) {
            float y = fmaf(ax, w1a[j], fmaf(ay, w1b[j], bb1[j]));
            y = fmaxf(y, 0.0f);
            t = fmaf(y, w2[j], t);
        }
        vv[m] = t * dinv;
    }
    if (lim == 2) {
        ((float2*)g_v)[i] = make_float2(vv[0], vv[1]);
        ((float2*)out)[i] = make_float2(vv[0], vv[1]);  // self-loop init
    } else {
        g_v[i0] = vv[0];
        out[i0] = vv[0];
    }
}

// ---------------------------------------------------------------- edge pass 2: out += v[src]
__global__ void k_edge2(const void* __restrict__ ei, float* __restrict__ out,
                        long long E, int n) {
    cudaTriggerProgrammaticLaunchCompletion();
    long long q = (long long)blockIdx.x * blockDim.x + threadIdx.x;
    long long e0 = 8 * q;
    if (e0 >= E) { cudaGridDependencySynchronize(); return; }
    if (e0 + 8 <= E) {
        const int* ps = (const int*)ei;
        const int* pd = (const int*)ei + E;
        int4 s0 = __ldcs((const int4*)(ps + e0));
        int4 d0 = __ldcs((const int4*)(pd + e0));
        int4 s1 = __ldcs((const int4*)(ps + e0) + 1);
        int4 d1 = __ldcs((const int4*)(pd + e0) + 1);
        cudaGridDependencySynchronize();       // wait for k_node2 (g_v, out init)
        if (g_is_i32) {
            int s[8] = {s0.x, s0.y, s0.z, s0.w, s1.x, s1.y, s1.z, s1.w};
            int d[8] = {d0.x, d0.y, d0.z, d0.w, d1.x, d1.y, d1.z, d1.w};
            float v[8];
#pragma unroll
            for (int k = 0; k < 8; k++)
                v[k] = ((unsigned)s[k] < (unsigned)n) ? __ldg(&g_v[s[k]]) : 0.0f;
#pragma unroll
            for (int k = 0; k < 8; k++)
                if ((unsigned)s[k] < (unsigned)n && (unsigned)d[k] < (unsigned)n)
                    atomicAdd(&out[d[k]], v[k]);
            return;
        }
    } else {
        cudaGridDependencySynchronize();
    }
    int is32 = g_is_i32;
    for (long long e = e0; e < e0 + 8 && e < E; e++) {
        int s = is32 ? ((const int*)ei)[e]     : (int)((const long long*)ei)[e];
        int d = is32 ? ((const int*)ei)[E + e] : (int)((const long long*)ei)[E + e];
        if ((unsigned)s < (unsigned)n && (unsigned)d < (unsigned)n)
            atomicAdd(&out[d], __ldg(&g_v[s]));
    }
}

// ---------------------------------------------------------------- final: scale + sigmoid
__global__ void k_final(float* __restrict__ out, const float* __restrict__ b2, int n) {
    float bb = __ldg(b2);                      // independent preamble
    cudaGridDependencySynchronize();           // wait for k_edge2 (out REDs)
    int i = blockIdx.x * blockDim.x + threadIdx.x;
    int i0 = 2 * i;
    if (i0 >= n) return;
    if (i0 + 1 < n) {
        float2 o  = ((const float2*)out)[i];
        float2 di = ((const float2*)g_dinv)[i];
        float z0 = fmaf(di.x, o.x, bb);
        float z1 = fmaf(di.y, o.y, bb);
        ((float2*)out)[i] = make_float2(1.0f / (1.0f + __expf(-z0)),
                                        1.0f / (1.0f + __expf(-z1)));
    } else {
        float z = fmaf(g_dinv[i0], out[i0], bb);
        out[i0] = 1.0f / (1.0f + __expf(-z));
    }
}

// ---------------------------------------------------------------- launch (PDL chain)
extern "C" void kernel_launch(void* const* d_in, const int* in_sizes, int n_in,
                              void* d_out, int out_size) {
    const float* x  = (const float*)d_in[0];
    const void*  ei = d_in[1];
    const float* W1 = (const float*)d_in[2];
    const float* b1 = (const float*)d_in[3];
    const float* W2 = (const float*)d_in[4];
    const float* b2 = (const float*)d_in[5];
    float* out = (float*)d_out;

    int       n = in_sizes[0] / 2;            // x is [N, 2]
    long long E = (long long)in_sizes[1] / 2; // edge_index is [2, E]

    const int T = 256;
    unsigned nb_half = (unsigned)(((n + 1) / 2 + T - 1) / T);
    long long noct = (E + 7) / 8;
    unsigned nb_edge = (unsigned)((noct + T - 1) / T);

    cudaLaunchAttribute attr[1];
    attr[0].id = cudaLaunchAttributeProgrammaticStreamSerialization;
    attr[0].val.programmaticStreamSerializationAllowed = 1;

    cudaLaunchConfig_t cfg = {};
    cfg.blockDim = dim3(T, 1, 1);
    cfg.stream = 0;

    // first kernel: normal launch (no PSS against harness's prior stream work)
    k_deg<<<nb_edge, T>>>(ei, E, n);

    cfg.attrs = attr; cfg.numAttrs = 1;

    cfg.gridDim = dim3(nb_half, 1, 1);
    cudaLaunchKernelEx(&cfg, k_node1, x, n);

    cfg.gridDim = dim3(nb_edge, 1, 1);
    cudaLaunchKernelEx(&cfg, k_edge1, ei, E, n);

    cfg.gridDim = dim3(nb_half, 1, 1);
    cudaLaunchKernelEx(&cfg, k_node2, W1, b1, W2, out, n);

    cfg.gridDim = dim3(nb_edge, 1, 1);
    cudaLaunchKernelEx(&cfg, k_edge2, ei, out, E, n);

    cfg.gridDim = dim3(nb_half, 1, 1);
    cudaLaunchKernelEx(&cfg, k_final, out, b2, n);
}